// round 4
// baseline (speedup 1.0000x reference)
#include <cuda_runtime.h>

// Problem constants
#define BN_B 4
#define TN_T 4096
#define DN_D 1024
#define HN_H 64
static constexpr long TT = (long)TN_T * TN_T;  // 16,777,216

// Static scratch (no allocations allowed)
__device__ float g_Q[(long)BN_B * TN_T * HN_H];           // 4 MB
__device__ float g_K[(long)BN_B * TN_T * HN_H];           // 4 MB
__device__ float g_V[(long)BN_B * TN_T * DN_D];           // 64 MB
__device__ float g_P[(long)BN_B * TN_T * TN_T];           // 268 MB (scores -> probs in place)

// ---------------------------------------------------------------------------
// Generic tiled SGEMM.
//   C[m,n] = scale * sum_k A[m,k] * B'[k,n]
//   BT=true : B is [N,K] row-major (B' = B^T), i.e. C = A * B^T
//   BT=false: B is [K,N] row-major,            i.e. C = A * B
//   CSKIP: skip tiles entirely above the causal diagonal (scores GEMM)
//   KLIM : limit k-loop to k < m0+BM (P·V GEMM; P upper triangle is zero)
// Per-batch strides sA/sB/sC applied with blockIdx.z.
// ---------------------------------------------------------------------------
template <int BM, int BN, int BK, int TM, int TN, bool BT, bool CSKIP, bool KLIM>
__global__ void hx_gemm(const float* __restrict__ A, const float* __restrict__ B,
                        float* __restrict__ C, int M, int N, int Kd,
                        long sA, long sB, long sC, float scale) {
    constexpr int THREADS = (BM / TM) * (BN / TN);
    const int m0 = blockIdx.y * BM;
    const int n0 = blockIdx.x * BN;
    if (CSKIP && n0 >= m0 + BM) return;  // fully masked tile

    const int b = blockIdx.z;
    A += (long)b * sA;
    B += (long)b * sB;
    C += (long)b * sC;

    __shared__ float As[BK][BM];
    __shared__ float Bs[BK][BN];

    const int tid = threadIdx.x;
    const int tx = tid % (BN / TN);
    const int ty = tid / (BN / TN);

    float acc[TM][TN];
#pragma unroll
    for (int i = 0; i < TM; i++)
#pragma unroll
        for (int j = 0; j < TN; j++) acc[i][j] = 0.f;

    int Kt = Kd / BK;
    if (KLIM) {
        int ke = (m0 + BM + BK - 1) / BK;
        if (ke < Kt) Kt = ke;
    }

    for (int kt = 0; kt < Kt; ++kt) {
        const int k0 = kt * BK;
        // Load A tile (BM x BK), store transposed As[k][m]
        constexpr int AV = BM * BK / 4;
        for (int v = tid; v < AV; v += THREADS) {
            int row = v / (BK / 4);
            int kc = (v % (BK / 4)) * 4;
            float4 t = *reinterpret_cast<const float4*>(A + (long)(m0 + row) * Kd + k0 + kc);
            As[kc + 0][row] = t.x;
            As[kc + 1][row] = t.y;
            As[kc + 2][row] = t.z;
            As[kc + 3][row] = t.w;
        }
        // Load B tile
        if (BT) {
            constexpr int BV = BN * BK / 4;
            for (int v = tid; v < BV; v += THREADS) {
                int row = v / (BK / 4);
                int kc = (v % (BK / 4)) * 4;
                float4 t = *reinterpret_cast<const float4*>(B + (long)(n0 + row) * Kd + k0 + kc);
                Bs[kc + 0][row] = t.x;
                Bs[kc + 1][row] = t.y;
                Bs[kc + 2][row] = t.z;
                Bs[kc + 3][row] = t.w;
            }
        } else {
            constexpr int BV = BN * BK / 4;
            for (int v = tid; v < BV; v += THREADS) {
                int row = v / (BN / 4);
                int nc = (v % (BN / 4)) * 4;
                *reinterpret_cast<float4*>(&Bs[row][nc]) =
                    *reinterpret_cast<const float4*>(B + (long)(k0 + row) * N + n0 + nc);
            }
        }
        __syncthreads();

#pragma unroll
        for (int k = 0; k < BK; k++) {
            float a[TM], bb[TN];
#pragma unroll
            for (int i = 0; i < TM; i++) a[i] = As[k][ty * TM + i];
#pragma unroll
            for (int j = 0; j < TN; j++) bb[j] = Bs[k][tx * TN + j];
#pragma unroll
            for (int i = 0; i < TM; i++)
#pragma unroll
                for (int j = 0; j < TN; j++) acc[i][j] += a[i] * bb[j];
        }
        __syncthreads();
    }

    // Epilogue
#pragma unroll
    for (int i = 0; i < TM; i++) {
        int m = m0 + ty * TM + i;
#pragma unroll
        for (int j = 0; j < TN; j += 4) {
            float4 t;
            t.x = acc[i][j + 0] * scale;
            t.y = acc[i][j + 1] * scale;
            t.z = acc[i][j + 2] * scale;
            t.w = acc[i][j + 3] * scale;
            *reinterpret_cast<float4*>(C + (long)m * N + n0 + tx * TN + j) = t;
        }
    }
}

// ---------------------------------------------------------------------------
// Row softmax over causal scores, in place. One 256-thread block per row.
// Writes normalized probs for s <= t, zeros for s > t (so P·V needs no mask).
// ---------------------------------------------------------------------------
__global__ void hx_softmax_rows(float* __restrict__ P) {
    const int t = blockIdx.x;
    const int b = blockIdx.y;
    float* row = P + (long)b * TT + (long)t * TN_T;
    const int len = t + 1;
    const int tid = threadIdx.x;

    __shared__ float shmax[8];
    __shared__ float shsum[8];

    float vals[16];
    int cnt = 0;
    float mx = -1e30f;
    for (int s = tid; s < len; s += 256) {
        float v = row[s];
        vals[cnt++] = v;
        mx = fmaxf(mx, v);
    }
    // block max
#pragma unroll
    for (int o = 16; o > 0; o >>= 1) mx = fmaxf(mx, __shfl_xor_sync(0xffffffffu, mx, o));
    if ((tid & 31) == 0) shmax[tid >> 5] = mx;
    __syncthreads();
    mx = shmax[0];
#pragma unroll
    for (int w = 1; w < 8; w++) mx = fmaxf(mx, shmax[w]);

    float sum = 0.f;
    for (int i = 0; i < cnt; i++) {
        vals[i] = __expf(vals[i] - mx);
        sum += vals[i];
    }
#pragma unroll
    for (int o = 16; o > 0; o >>= 1) sum += __shfl_xor_sync(0xffffffffu, sum, o);
    if ((tid & 31) == 0) shsum[tid >> 5] = sum;
    __syncthreads();
    sum = shsum[0];
#pragma unroll
    for (int w = 1; w < 8; w++) sum += shsum[w];

    const float inv = 1.f / sum;
    cnt = 0;
    for (int s = tid; s < len; s += 256) row[s] = vals[cnt++] * inv;
    // zero upper triangle so the P·V GEMM can run unmasked over padded k-tiles
    for (int s = tid; s < TN_T; s += 256)
        if (s >= len) row[s] = 0.f;
}

extern "C" void kernel_launch(void* const* d_in, const int* in_sizes, int n_in,
                              void* d_out, int out_size) {
    const float* x = (const float*)d_in[0];   // [4, 4096, 1024]
    const float* Wk = (const float*)d_in[1];  // [64, 1024]
    const float* Wq = (const float*)d_in[2];  // [64, 1024]
    const float* Wv = (const float*)d_in[3];  // [1024, 1024]
    float* out = (float*)d_out;               // [4, 4096, 1024] fp32

    float *Qp, *Kp, *Vp, *Pp;
    cudaGetSymbolAddress((void**)&Qp, g_Q);
    cudaGetSymbolAddress((void**)&Kp, g_K);
    cudaGetSymbolAddress((void**)&Vp, g_V);
    cudaGetSymbolAddress((void**)&Pp, g_P);

    const int MT = BN_B * TN_T;  // 16384 flattened rows
    const float qk_scale = 0.125f;  // 1/sqrt(64)

    // Q = x * Wq^T, K = x * Wk^T   ([16384,1024] x [64,1024]^T)
    dim3 gqk(1, MT / 128, 1);
    hx_gemm<128, 64, 8, 8, 4, true, false, false><<<gqk, 256>>>(
        x, Wq, Qp, MT, HN_H, DN_D, 0, 0, 0, 1.f);
    hx_gemm<128, 64, 8, 8, 4, true, false, false><<<gqk, 256>>>(
        x, Wk, Kp, MT, HN_H, DN_D, 0, 0, 0, 1.f);

    // V = x * Wv^T   ([16384,1024] x [1024,1024]^T)
    hx_gemm<128, 128, 8, 8, 8, true, false, false><<<dim3(DN_D / 128, MT / 128, 1), 256>>>(
        x, Wv, Vp, MT, DN_D, DN_D, 0, 0, 0, 1.f);

    // S = scale * Q * K^T per batch, causal tiles only
    hx_gemm<128, 128, 8, 8, 8, true, true, false><<<dim3(TN_T / 128, TN_T / 128, BN_B), 256>>>(
        Qp, Kp, Pp, TN_T, TN_T, HN_H,
        (long)TN_T * HN_H, (long)TN_T * HN_H, TT, qk_scale);

    // softmax rows in place (zero-fills upper triangle)
    hx_softmax_rows<<<dim3(TN_T, BN_B), 256>>>(Pp);

    // out = P * V per batch, k-loop limited to causal extent
    hx_gemm<128, 128, 8, 8, 8, false, false, true><<<dim3(DN_D / 128, TN_T / 128, BN_B), 256>>>(
        Pp, Vp, out, TN_T, DN_D, TN_T,
        TT, (long)TN_T * DN_D, (long)TN_T * DN_D, 1.f);
}

// round 7
// speedup vs baseline: 2.8249x; 2.8249x over previous
#include <cuda_runtime.h>
#include <cstdint>

// Problem constants
#define BN_B 4
#define TN_T 4096
#define DN_D 1024
#define HN_H 64
static constexpr long TT = (long)TN_T * TN_T;  // 16,777,216

// Static scratch (no allocations allowed)
__device__ float g_Q[(long)BN_B * TN_T * HN_H];            // 4 MB
__device__ float g_K[(long)BN_B * TN_T * HN_H];            // 4 MB
__device__ float g_Vt[(long)DN_D * BN_B * TN_T];           // 64 MB, Vt[e][b*T+t]
__device__ float g_P[(long)BN_B * TN_T * TN_T];            // 268 MB

// ============================================================================
// PTX helpers (arch-stable features only: ldmatrix sm_75+, tf32 mma sm_80+)
// ============================================================================
__device__ __forceinline__ uint32_t smem_u32(const void* p) {
    uint32_t a;
    asm("{ .reg .u64 t; cvta.to.shared.u64 t, %1; cvt.u32.u64 %0, t; }"
        : "=r"(a) : "l"(p));
    return a;
}
__device__ __forceinline__ uint32_t f2tf32(float x) {
    uint32_t r; asm("cvt.rna.tf32.f32 %0, %1;" : "=r"(r) : "f"(x)); return r;
}
__device__ __forceinline__ void ldmx4(uint32_t* r, uint32_t addr) {
    asm volatile("ldmatrix.sync.aligned.m8n8.x4.shared.b16 {%0,%1,%2,%3}, [%4];"
                 : "=r"(r[0]), "=r"(r[1]), "=r"(r[2]), "=r"(r[3]) : "r"(addr));
}
__device__ __forceinline__ void mma_tf32(float* c, const uint32_t* a, const uint32_t* b) {
    asm volatile(
        "mma.sync.aligned.m16n8k8.row.col.f32.tf32.tf32.f32 "
        "{%0,%1,%2,%3}, {%4,%5,%6,%7}, {%8,%9}, {%0,%1,%2,%3};"
        : "+f"(c[0]), "+f"(c[1]), "+f"(c[2]), "+f"(c[3])
        : "r"(a[0]), "r"(a[1]), "r"(a[2]), "r"(a[3]), "r"(b[0]), "r"(b[1]));
}
__device__ __forceinline__ uint32_t sw128(uint32_t off) {
    return off ^ ((off >> 3) & 0x70);
}

// ============================================================================
// Warp-MMA tf32 GEMM:  C[m,n] = sum_k A[m,k] * B[n,k]   (both K-major fp32)
// 128x128 CTA tile, BK=32, 8 warps (2x4), warp tile 64x32, m16n8k8 mma.
// Double-buffered smem (2 x 32KB), register-staged gmem pipeline.
// KLIM: limit k to m0+128 (causal P.V; P upper triangle is zero).
// ============================================================================
static constexpr int MMA_SMEM = 65536;  // 2 stages x (16KB A + 16KB B)

template <bool KLIM>
__global__ __launch_bounds__(256)
void hx_mma_nt(const float* __restrict__ A, const float* __restrict__ B,
               float* __restrict__ C, int lda, int ldb, int ldc, int Kd,
               long sA, long sB, long sC) {
    extern __shared__ char sm[];
    const int tid = threadIdx.x;
    const int wid = tid >> 5;
    const int lane = tid & 31;
    const int m0 = blockIdx.y * 128;
    const int n0 = blockIdx.x * 128;
    const int bz = blockIdx.z;
    A += (long)bz * sA + (long)m0 * lda;
    B += (long)bz * sB + (long)n0 * ldb;
    C += (long)bz * sC;

    int nchunks = Kd >> 5;
    if (KLIM) { int ke = (m0 + 128) >> 5; if (ke < nchunks) nchunks = ke; }

    const int wm = (wid >> 2) * 64;  // warp row base (2 warps along M)
    const int wn = (wid & 3) * 32;   // warp col base (4 warps along N)
    const uint32_t smbase = smem_u32(sm);

    // Loader geometry: 1024 float4 per 128x32 tile, 4 per thread.
    const int lrow = tid >> 1;              // not used; explicit below
    (void)lrow;

    float acc[4][4][4];
#pragma unroll
    for (int mt = 0; mt < 4; mt++)
#pragma unroll
        for (int nt = 0; nt < 4; nt++)
#pragma unroll
            for (int i = 0; i < 4; i++) acc[mt][nt][i] = 0.f;

    float4 ra[4], rb[4];

    // --- prologue: load chunk 0 ---
#pragma unroll
    for (int i = 0; i < 4; i++) {
        int idx = i * 256 + tid;
        int row = idx >> 3, c4 = idx & 7;
        ra[i] = *(const float4*)(A + (long)row * lda + c4 * 4);
        rb[i] = *(const float4*)(B + (long)row * ldb + c4 * 4);
    }
#pragma unroll
    for (int i = 0; i < 4; i++) {
        int idx = i * 256 + tid;
        int row = idx >> 3, c4 = idx & 7;
        uint32_t off = sw128((uint32_t)(row * 128 + c4 * 16));
        uint4 ta = {f2tf32(ra[i].x), f2tf32(ra[i].y), f2tf32(ra[i].z), f2tf32(ra[i].w)};
        *(uint4*)(sm + off) = ta;
        uint4 tb = {f2tf32(rb[i].x), f2tf32(rb[i].y), f2tf32(rb[i].z), f2tf32(rb[i].w)};
        *(uint4*)(sm + 16384 + off) = tb;
    }
    __syncthreads();

    for (int kt = 0; kt < nchunks; ++kt) {
        const bool more = (kt + 1 < nchunks);
        if (more) {
            const float* gA = A + (kt + 1) * 32;
            const float* gB = B + (kt + 1) * 32;
#pragma unroll
            for (int i = 0; i < 4; i++) {
                int idx = i * 256 + tid;
                int row = idx >> 3, c4 = idx & 7;
                ra[i] = *(const float4*)(gA + (long)row * lda + c4 * 4);
                rb[i] = *(const float4*)(gB + (long)row * ldb + c4 * 4);
            }
        }

        const uint32_t sa = smbase + (uint32_t)(kt & 1) * 32768u;
        const uint32_t sb = sa + 16384u;
        const int sub = lane >> 3, r8 = lane & 7;

#pragma unroll
        for (int ks = 0; ks < 4; ks++) {
            uint32_t af[4][4];
#pragma unroll
            for (int mt = 0; mt < 4; mt++) {
                int row = wm + mt * 16 + ((sub & 1) << 3) + r8;
                int kseg = ks * 32 + ((sub >> 1) << 4);
                ldmx4(af[mt], sa + sw128((uint32_t)(row * 128 + kseg)));
            }
            uint32_t bf[4][2];
#pragma unroll
            for (int j2 = 0; j2 < 2; j2++) {
                int row = wn + j2 * 16 + ((sub >> 1) << 3) + r8;
                int kseg = ks * 32 + ((sub & 1) << 4);
                uint32_t r[4];
                ldmx4(r, sb + sw128((uint32_t)(row * 128 + kseg)));
                bf[j2 * 2 + 0][0] = r[0];
                bf[j2 * 2 + 0][1] = r[1];
                bf[j2 * 2 + 1][0] = r[2];
                bf[j2 * 2 + 1][1] = r[3];
            }
#pragma unroll
            for (int mt = 0; mt < 4; mt++)
#pragma unroll
                for (int nt = 0; nt < 4; nt++)
                    mma_tf32(acc[mt][nt], af[mt], bf[nt]);
        }

        if (more) {
            char* da = sm + ((kt + 1) & 1) * 32768;
#pragma unroll
            for (int i = 0; i < 4; i++) {
                int idx = i * 256 + tid;
                int row = idx >> 3, c4 = idx & 7;
                uint32_t off = sw128((uint32_t)(row * 128 + c4 * 16));
                uint4 ta = {f2tf32(ra[i].x), f2tf32(ra[i].y), f2tf32(ra[i].z), f2tf32(ra[i].w)};
                *(uint4*)(da + off) = ta;
                uint4 tb = {f2tf32(rb[i].x), f2tf32(rb[i].y), f2tf32(rb[i].z), f2tf32(rb[i].w)};
                *(uint4*)(da + 16384 + off) = tb;
            }
        }
        __syncthreads();
    }

    // Epilogue: standard m16n8 fragment layout
    const int r0 = m0 + wm + (lane >> 2);
    const int c0 = n0 + wn + (lane & 3) * 2;
#pragma unroll
    for (int mt = 0; mt < 4; mt++) {
#pragma unroll
        for (int nt = 0; nt < 4; nt++) {
            long row = r0 + mt * 16;
            int col = c0 + nt * 8;
            float2 lo = {acc[mt][nt][0], acc[mt][nt][1]};
            float2 hi = {acc[mt][nt][2], acc[mt][nt][3]};
            *(float2*)(C + row * ldc + col) = lo;
            *(float2*)(C + (row + 8) * ldc + col) = hi;
        }
    }
}

// ---------------------------------------------------------------------------
// fp32 SIMT tiled GEMM (QK projections + scores; precision-critical, cheap)
// ---------------------------------------------------------------------------
template <int BM, int BN, int BK, int TM, int TN, bool BT, bool CSKIP, bool KLIM>
__global__ void hx_gemm(const float* __restrict__ A, const float* __restrict__ B,
                        float* __restrict__ C, int M, int N, int Kd,
                        long sA, long sB, long sC, float scale) {
    constexpr int THREADS = (BM / TM) * (BN / TN);
    const int m0 = blockIdx.y * BM;
    const int n0 = blockIdx.x * BN;
    if (CSKIP && n0 >= m0 + BM) return;

    const int b = blockIdx.z;
    A += (long)b * sA;
    B += (long)b * sB;
    C += (long)b * sC;

    __shared__ float As[BK][BM];
    __shared__ float Bs[BK][BN];

    const int tid = threadIdx.x;
    const int tx = tid % (BN / TN);
    const int ty = tid / (BN / TN);

    float acc[TM][TN];
#pragma unroll
    for (int i = 0; i < TM; i++)
#pragma unroll
        for (int j = 0; j < TN; j++) acc[i][j] = 0.f;

    int Kt = Kd / BK;
    if (KLIM) {
        int ke = (m0 + BM + BK - 1) / BK;
        if (ke < Kt) Kt = ke;
    }

    for (int kt = 0; kt < Kt; ++kt) {
        const int k0 = kt * BK;
        constexpr int AV = BM * BK / 4;
        for (int v = tid; v < AV; v += THREADS) {
            int row = v / (BK / 4);
            int kc = (v % (BK / 4)) * 4;
            float4 t = *reinterpret_cast<const float4*>(A + (long)(m0 + row) * Kd + k0 + kc);
            As[kc + 0][row] = t.x;
            As[kc + 1][row] = t.y;
            As[kc + 2][row] = t.z;
            As[kc + 3][row] = t.w;
        }
        if (BT) {
            constexpr int BV = BN * BK / 4;
            for (int v = tid; v < BV; v += THREADS) {
                int row = v / (BK / 4);
                int kc = (v % (BK / 4)) * 4;
                float4 t = *reinterpret_cast<const float4*>(B + (long)(n0 + row) * Kd + k0 + kc);
                Bs[kc + 0][row] = t.x;
                Bs[kc + 1][row] = t.y;
                Bs[kc + 2][row] = t.z;
                Bs[kc + 3][row] = t.w;
            }
        } else {
            constexpr int BV = BN * BK / 4;
            for (int v = tid; v < BV; v += THREADS) {
                int row = v / (BN / 4);
                int nc = (v % (BN / 4)) * 4;
                *reinterpret_cast<float4*>(&Bs[row][nc]) =
                    *reinterpret_cast<const float4*>(B + (long)(k0 + row) * N + n0 + nc);
            }
        }
        __syncthreads();

#pragma unroll
        for (int k = 0; k < BK; k++) {
            float a[TM], bb[TN];
#pragma unroll
            for (int i = 0; i < TM; i++) a[i] = As[k][ty * TM + i];
#pragma unroll
            for (int j = 0; j < TN; j++) bb[j] = Bs[k][tx * TN + j];
#pragma unroll
            for (int i = 0; i < TM; i++)
#pragma unroll
                for (int j = 0; j < TN; j++) acc[i][j] += a[i] * bb[j];
        }
        __syncthreads();
    }

#pragma unroll
    for (int i = 0; i < TM; i++) {
        int m = m0 + ty * TM + i;
#pragma unroll
        for (int j = 0; j < TN; j += 4) {
            float4 t;
            t.x = acc[i][j + 0] * scale;
            t.y = acc[i][j + 1] * scale;
            t.z = acc[i][j + 2] * scale;
            t.w = acc[i][j + 3] * scale;
            *reinterpret_cast<float4*>(C + (long)m * N + n0 + tx * TN + j) = t;
        }
    }
}

// ---------------------------------------------------------------------------
// Row softmax over causal scores, in place; zero-fills upper triangle.
// ---------------------------------------------------------------------------
__global__ void hx_softmax_rows(float* __restrict__ P) {
    const int t = blockIdx.x;
    const int b = blockIdx.y;
    float* row = P + (long)b * TT + (long)t * TN_T;
    const int len = t + 1;
    const int tid = threadIdx.x;

    __shared__ float shmax[8];
    __shared__ float shsum[8];

    float vals[16];
    int cnt = 0;
    float mx = -1e30f;
    for (int s = tid; s < len; s += 256) {
        float v = row[s];
        vals[cnt++] = v;
        mx = fmaxf(mx, v);
    }
#pragma unroll
    for (int o = 16; o > 0; o >>= 1) mx = fmaxf(mx, __shfl_xor_sync(0xffffffffu, mx, o));
    if ((tid & 31) == 0) shmax[tid >> 5] = mx;
    __syncthreads();
    mx = shmax[0];
#pragma unroll
    for (int w = 1; w < 8; w++) mx = fmaxf(mx, shmax[w]);

    float sum = 0.f;
    for (int i = 0; i < cnt; i++) {
        vals[i] = __expf(vals[i] - mx);
        sum += vals[i];
    }
#pragma unroll
    for (int o = 16; o > 0; o >>= 1) sum += __shfl_xor_sync(0xffffffffu, sum, o);
    if ((tid & 31) == 0) shsum[tid >> 5] = sum;
    __syncthreads();
    sum = shsum[0];
#pragma unroll
    for (int w = 1; w < 8; w++) sum += shsum[w];

    const float inv = 1.f / sum;
    cnt = 0;
    for (int s = tid; s < len; s += 256) row[s] = vals[cnt++] * inv;
    for (int s = tid; s < TN_T; s += 256)
        if (s >= len) row[s] = 0.f;
}

extern "C" void kernel_launch(void* const* d_in, const int* in_sizes, int n_in,
                              void* d_out, int out_size) {
    const float* x = (const float*)d_in[0];   // [4, 4096, 1024]
    const float* Wk = (const float*)d_in[1];  // [64, 1024]
    const float* Wq = (const float*)d_in[2];  // [64, 1024]
    const float* Wv = (const float*)d_in[3];  // [1024, 1024]
    float* out = (float*)d_out;               // [4, 4096, 1024] fp32

    float *Qp, *Kp, *Vtp, *Pp;
    cudaGetSymbolAddress((void**)&Qp, g_Q);
    cudaGetSymbolAddress((void**)&Kp, g_K);
    cudaGetSymbolAddress((void**)&Vtp, g_Vt);
    cudaGetSymbolAddress((void**)&Pp, g_P);

    // Opt in to 64KB dynamic smem for the mma kernels (idempotent, no alloc).
    cudaFuncSetAttribute(hx_mma_nt<false>,
                         cudaFuncAttributeMaxDynamicSharedMemorySize, MMA_SMEM);
    cudaFuncSetAttribute(hx_mma_nt<true>,
                         cudaFuncAttributeMaxDynamicSharedMemorySize, MMA_SMEM);

    const int MT = BN_B * TN_T;     // 16384 flattened token rows
    const float qk_scale = 0.125f;  // 1/sqrt(64)

    // Q = x * Wq^T, K = x * Wk^T  (fp32 SIMT — precision-critical pre-softmax)
    dim3 gqk(1, MT / 128, 1);
    hx_gemm<128, 64, 8, 8, 4, true, false, false><<<gqk, 256>>>(
        x, Wq, Qp, MT, HN_H, DN_D, 0, 0, 0, 1.f);
    hx_gemm<128, 64, 8, 8, 4, true, false, false><<<gqk, 256>>>(
        x, Wk, Kp, MT, HN_H, DN_D, 0, 0, 0, 1.f);

    // Vt = Wv * x^T  (tf32 warp-mma; gives V transposed for free)
    hx_mma_nt<false><<<dim3(MT / 128, DN_D / 128, 1), 256, MMA_SMEM>>>(
        Wv, x, Vtp, DN_D, DN_D, MT, DN_D, 0, 0, 0);

    // S = scale * Q * K^T per batch (fp32 SIMT, causal tiles only)
    hx_gemm<128, 128, 8, 8, 8, true, true, false><<<dim3(TN_T / 128, TN_T / 128, BN_B), 256>>>(
        Qp, Kp, Pp, TN_T, TN_T, HN_H,
        (long)TN_T * HN_H, (long)TN_T * HN_H, TT, qk_scale);

    // softmax rows in place (zero-fills upper triangle)
    hx_softmax_rows<<<dim3(TN_T, BN_B), 256>>>(Pp);

    // out = P * V per batch (tf32 warp-mma, causal k-limit)
    // C[t,e] = sum_s P[t,s] * Vt[e, b*4096+s]
    hx_mma_nt<true><<<dim3(DN_D / 128, TN_T / 128, BN_B), 256, MMA_SMEM>>>(
        Pp, Vtp, out, TN_T, (int)MT, DN_D, TN_T,
        TT, (long)TN_T, (long)TN_T * DN_D);
}

// round 8
// speedup vs baseline: 3.8994x; 1.3804x over previous
#include <cuda_runtime.h>
#include <cstdint>

// Problem constants
#define BN_B 4
#define TN_T 4096
#define DN_D 1024
#define HN_H 64
static constexpr long TT = (long)TN_T * TN_T;  // 16,777,216

// Static scratch (no allocations allowed)
__device__ float g_Q[(long)BN_B * TN_T * HN_H];            // 4 MB
__device__ float g_K[(long)BN_B * TN_T * HN_H];            // 4 MB
__device__ float g_Vt[(long)DN_D * BN_B * TN_T];           // 64 MB, Vt[e][b*T+t] (tf32-rounded)
__device__ float g_P[(long)BN_B * TN_T * TN_T];            // 268 MB (tf32-rounded after softmax)
__device__ float g_xr[(long)BN_B * TN_T * DN_D];           // 64 MB, tf32-rounded x
__device__ float g_Wvr[(long)DN_D * DN_D];                 // 4 MB, tf32-rounded Wv

// ============================================================================
// PTX helpers (arch-stable: ldmatrix sm_75+, tf32 mma sm_80+, cp.async sm_80+)
// ============================================================================
__device__ __forceinline__ uint32_t smem_u32(const void* p) {
    uint32_t a;
    asm("{ .reg .u64 t; cvta.to.shared.u64 t, %1; cvt.u32.u64 %0, t; }"
        : "=r"(a) : "l"(p));
    return a;
}
__device__ __forceinline__ uint32_t f2tf32(float x) {
    uint32_t r; asm("cvt.rna.tf32.f32 %0, %1;" : "=r"(r) : "f"(x)); return r;
}
__device__ __forceinline__ float roundtf(float x) {
    return __uint_as_float(f2tf32(x));
}
__device__ __forceinline__ void ldmx4(uint32_t* r, uint32_t addr) {
    asm volatile("ldmatrix.sync.aligned.m8n8.x4.shared.b16 {%0,%1,%2,%3}, [%4];"
                 : "=r"(r[0]), "=r"(r[1]), "=r"(r[2]), "=r"(r[3]) : "r"(addr));
}
__device__ __forceinline__ void mma_tf32(float* c, const uint32_t* a, const uint32_t* b) {
    asm volatile(
        "mma.sync.aligned.m16n8k8.row.col.f32.tf32.tf32.f32 "
        "{%0,%1,%2,%3}, {%4,%5,%6,%7}, {%8,%9}, {%0,%1,%2,%3};"
        : "+f"(c[0]), "+f"(c[1]), "+f"(c[2]), "+f"(c[3])
        : "r"(a[0]), "r"(a[1]), "r"(a[2]), "r"(a[3]), "r"(b[0]), "r"(b[1]));
}
__device__ __forceinline__ void cpasync16(uint32_t dst, const void* src) {
    asm volatile("cp.async.cg.shared.global [%0], [%1], 16;" :: "r"(dst), "l"(src));
}
__device__ __forceinline__ uint32_t sw128(uint32_t off) {
    return off ^ ((off >> 3) & 0x70);
}

// ============================================================================
// Warp-MMA tf32 GEMM:  C[m,n] = sum_k A[m,k] * B[n,k]   (both K-major,
// PRE-ROUNDED to tf32). 128x128 CTA tile, BK=32, 8 warps (2x4), warp 64x32.
// 3-stage cp.async pipeline (96KB smem), one __syncthreads per chunk.
// KLIM: limit k to m0+128 (causal P.V); also reverses blockIdx.y so the
//       deepest tiles launch first (load balance).
// ROUND: round epilogue output to tf32 (Vt producer).
// ============================================================================
static constexpr int MMA_SMEM = 3 * 32768;  // 3 stages x (16KB A + 16KB B)

template <bool KLIM, bool ROUND>
__global__ __launch_bounds__(256, 2)
void hx_mma_nt(const float* __restrict__ A, const float* __restrict__ B,
               float* __restrict__ C, int lda, int ldb, int ldc, int Kd,
               long sA, long sB, long sC) {
    extern __shared__ char sm[];
    const int tid = threadIdx.x;
    const int wid = tid >> 5;
    const int lane = tid & 31;
    const int myy = KLIM ? ((int)gridDim.y - 1 - (int)blockIdx.y) : (int)blockIdx.y;
    const int m0 = myy * 128;
    const int n0 = blockIdx.x * 128;
    A += (long)blockIdx.z * sA + (long)m0 * lda;
    B += (long)blockIdx.z * sB + (long)n0 * ldb;
    C += (long)blockIdx.z * sC;

    int nchunks = Kd >> 5;
    if (KLIM) { int ke = (m0 + 128) >> 5; if (ke < nchunks) nchunks = ke; }

    const int wm = (wid >> 2) * 64;
    const int wn = (wid & 3) * 32;
    const uint32_t smb = smem_u32(sm);

    float acc[4][4][4];
#pragma unroll
    for (int mt = 0; mt < 4; mt++)
#pragma unroll
        for (int nt = 0; nt < 4; nt++)
#pragma unroll
            for (int i = 0; i < 4; i++) acc[mt][nt][i] = 0.f;

    // --- async loader for one 128x32 chunk pair into a stage ---
    auto load_chunk = [&](int kt, int stage) {
        const float* gA = A + kt * 32;
        const float* gB = B + kt * 32;
        const uint32_t sa = smb + (uint32_t)stage * 32768u;
#pragma unroll
        for (int i = 0; i < 4; i++) {
            int idx = i * 256 + tid;
            int row = idx >> 3, c4 = idx & 7;
            uint32_t off = sw128((uint32_t)(row * 128 + c4 * 16));
            cpasync16(sa + off, gA + (long)row * lda + c4 * 4);
            cpasync16(sa + 16384u + off, gB + (long)row * ldb + c4 * 4);
        }
    };

    // prologue: chunks 0 and 1
    if (0 < nchunks) load_chunk(0, 0);
    asm volatile("cp.async.commit_group;" ::: "memory");
    if (1 < nchunks) load_chunk(1, 1);
    asm volatile("cp.async.commit_group;" ::: "memory");

    for (int kt = 0; kt < nchunks; ++kt) {
        asm volatile("cp.async.wait_group 1;" ::: "memory");
        __syncthreads();  // chunk kt ready; stage (kt+2)%3 fully consumed

        const int nk = kt + 2;
        if (nk < nchunks) load_chunk(nk, nk % 3);
        asm volatile("cp.async.commit_group;" ::: "memory");

        const uint32_t sa = smb + (uint32_t)(kt % 3) * 32768u;
        const uint32_t sb = sa + 16384u;
        const int sub = lane >> 3, r8 = lane & 7;

#pragma unroll
        for (int ks = 0; ks < 4; ks++) {
            uint32_t af[4][4];
#pragma unroll
            for (int mt = 0; mt < 4; mt++) {
                int row = wm + mt * 16 + ((sub & 1) << 3) + r8;
                int kseg = ks * 32 + ((sub >> 1) << 4);
                ldmx4(af[mt], sa + sw128((uint32_t)(row * 128 + kseg)));
            }
            uint32_t bf[4][2];
#pragma unroll
            for (int j2 = 0; j2 < 2; j2++) {
                int row = wn + j2 * 16 + ((sub >> 1) << 3) + r8;
                int kseg = ks * 32 + ((sub & 1) << 4);
                uint32_t r[4];
                ldmx4(r, sb + sw128((uint32_t)(row * 128 + kseg)));
                bf[j2 * 2 + 0][0] = r[0];
                bf[j2 * 2 + 0][1] = r[1];
                bf[j2 * 2 + 1][0] = r[2];
                bf[j2 * 2 + 1][1] = r[3];
            }
#pragma unroll
            for (int mt = 0; mt < 4; mt++)
#pragma unroll
                for (int nt = 0; nt < 4; nt++)
                    mma_tf32(acc[mt][nt], af[mt], bf[nt]);
        }
    }

    // Epilogue: standard m16n8 fragment layout
    const int r0 = m0 + wm + (lane >> 2);
    const int c0 = n0 + wn + (lane & 3) * 2;
#pragma unroll
    for (int mt = 0; mt < 4; mt++) {
#pragma unroll
        for (int nt = 0; nt < 4; nt++) {
            long row = r0 + mt * 16;
            int col = c0 + nt * 8;
            float2 lo, hi;
            if (ROUND) {
                lo = {roundtf(acc[mt][nt][0]), roundtf(acc[mt][nt][1])};
                hi = {roundtf(acc[mt][nt][2]), roundtf(acc[mt][nt][3])};
            } else {
                lo = {acc[mt][nt][0], acc[mt][nt][1]};
                hi = {acc[mt][nt][2], acc[mt][nt][3]};
            }
            *(float2*)(C + row * ldc + col) = lo;
            *(float2*)(C + (row + 8) * ldc + col) = hi;
        }
    }
}

// ---------------------------------------------------------------------------
// Fused Q/K projection: reads x ONCE, computes Q = x*Wq^T and K = x*Wk^T
// (fp32, precision-critical), and emits tf32-rounded x_r as a side product.
// BM=128, BK=32, 256 threads, 8x8 microtile over a 128-wide fused N (64 Q cols
// then 64 K cols).
// ---------------------------------------------------------------------------
__global__ __launch_bounds__(256)
void hx_qk(const float* __restrict__ x, const float* __restrict__ Wq,
           const float* __restrict__ Wk, float* __restrict__ Q,
           float* __restrict__ Kout, float* __restrict__ xr) {
    __shared__ float As[32][128];
    __shared__ float Bs[32][128];
    const int tid = threadIdx.x;
    const int m0 = blockIdx.x * 128;
    const int tx = tid & 15, ty = tid >> 4;

    float acc[8][8];
#pragma unroll
    for (int i = 0; i < 8; i++)
#pragma unroll
        for (int j = 0; j < 8; j++) acc[i][j] = 0.f;

    for (int kt = 0; kt < 32; ++kt) {
        const int k0 = kt * 32;
#pragma unroll
        for (int i = 0; i < 4; i++) {
            int v = i * 256 + tid;
            int row = v >> 3, kc = (v & 7) * 4;
            const float* src = x + (long)(m0 + row) * DN_D + k0 + kc;
            float4 t = *(const float4*)src;
            As[kc + 0][row] = t.x;
            As[kc + 1][row] = t.y;
            As[kc + 2][row] = t.z;
            As[kc + 3][row] = t.w;
            uint4 r = {f2tf32(t.x), f2tf32(t.y), f2tf32(t.z), f2tf32(t.w)};
            *(uint4*)(xr + (long)(m0 + row) * DN_D + k0 + kc) = r;
        }
#pragma unroll
        for (int i = 0; i < 4; i++) {
            int v = i * 256 + tid;
            if (v < 512) {
                int row = v >> 3, kc = (v & 7) * 4;
                float4 t = *(const float4*)(Wq + (long)row * DN_D + k0 + kc);
                Bs[kc + 0][row] = t.x;
                Bs[kc + 1][row] = t.y;
                Bs[kc + 2][row] = t.z;
                Bs[kc + 3][row] = t.w;
            } else {
                int w = v - 512;
                int row = w >> 3, kc = (w & 7) * 4;
                float4 t = *(const float4*)(Wk + (long)row * DN_D + k0 + kc);
                Bs[kc + 0][64 + row] = t.x;
                Bs[kc + 1][64 + row] = t.y;
                Bs[kc + 2][64 + row] = t.z;
                Bs[kc + 3][64 + row] = t.w;
            }
        }
        __syncthreads();

#pragma unroll
        for (int k = 0; k < 32; k++) {
            float a[8], bb[8];
#pragma unroll
            for (int i = 0; i < 8; i++) a[i] = As[k][ty * 8 + i];
#pragma unroll
            for (int j = 0; j < 8; j++) bb[j] = Bs[k][tx * 8 + j];
#pragma unroll
            for (int i = 0; i < 8; i++)
#pragma unroll
                for (int j = 0; j < 8; j++) acc[i][j] += a[i] * bb[j];
        }
        __syncthreads();
    }

    float* dst = (tx < 8) ? Q : Kout;
    const int cbase = (tx < 8) ? tx * 8 : (tx - 8) * 8;
#pragma unroll
    for (int i = 0; i < 8; i++) {
        long m = m0 + ty * 8 + i;
#pragma unroll
        for (int j = 0; j < 8; j += 4) {
            float4 t = {acc[i][j], acc[i][j + 1], acc[i][j + 2], acc[i][j + 3]};
            *(float4*)(dst + m * HN_H + cbase + j) = t;
        }
    }
}

// ---------------------------------------------------------------------------
// tf32 rounding pass (for Wv)
// ---------------------------------------------------------------------------
__global__ void hx_round4(const float* __restrict__ src, float* __restrict__ dst) {
    long i = ((long)blockIdx.x * 256 + threadIdx.x) * 4;
    float4 t = *(const float4*)(src + i);
    uint4 r = {f2tf32(t.x), f2tf32(t.y), f2tf32(t.z), f2tf32(t.w)};
    *(uint4*)(dst + i) = r;
}

// ---------------------------------------------------------------------------
// fp32 SIMT tiled GEMM (scores; precision-critical)
// ---------------------------------------------------------------------------
template <int BM, int BN, int BK, int TM, int TN, bool BT, bool CSKIP, bool KLIM>
__global__ void hx_gemm(const float* __restrict__ A, const float* __restrict__ B,
                        float* __restrict__ C, int M, int N, int Kd,
                        long sA, long sB, long sC, float scale) {
    constexpr int THREADS = (BM / TM) * (BN / TN);
    const int m0 = blockIdx.y * BM;
    const int n0 = blockIdx.x * BN;
    if (CSKIP && n0 >= m0 + BM) return;

    const int b = blockIdx.z;
    A += (long)b * sA;
    B += (long)b * sB;
    C += (long)b * sC;

    __shared__ float As[BK][BM];
    __shared__ float Bs[BK][BN];

    const int tid = threadIdx.x;
    const int tx = tid % (BN / TN);
    const int ty = tid / (BN / TN);

    float acc[TM][TN];
#pragma unroll
    for (int i = 0; i < TM; i++)
#pragma unroll
        for (int j = 0; j < TN; j++) acc[i][j] = 0.f;

    int Kt = Kd / BK;
    if (KLIM) {
        int ke = (m0 + BM + BK - 1) / BK;
        if (ke < Kt) Kt = ke;
    }

    for (int kt = 0; kt < Kt; ++kt) {
        const int k0 = kt * BK;
        constexpr int AV = BM * BK / 4;
        for (int v = tid; v < AV; v += THREADS) {
            int row = v / (BK / 4);
            int kc = (v % (BK / 4)) * 4;
            float4 t = *reinterpret_cast<const float4*>(A + (long)(m0 + row) * Kd + k0 + kc);
            As[kc + 0][row] = t.x;
            As[kc + 1][row] = t.y;
            As[kc + 2][row] = t.z;
            As[kc + 3][row] = t.w;
        }
        if (BT) {
            constexpr int BV = BN * BK / 4;
            for (int v = tid; v < BV; v += THREADS) {
                int row = v / (BK / 4);
                int kc = (v % (BK / 4)) * 4;
                float4 t = *reinterpret_cast<const float4*>(B + (long)(n0 + row) * Kd + k0 + kc);
                Bs[kc + 0][row] = t.x;
                Bs[kc + 1][row] = t.y;
                Bs[kc + 2][row] = t.z;
                Bs[kc + 3][row] = t.w;
            }
        } else {
            constexpr int BV = BN * BK / 4;
            for (int v = tid; v < BV; v += THREADS) {
                int row = v / (BN / 4);
                int nc = (v % (BN / 4)) * 4;
                *reinterpret_cast<float4*>(&Bs[row][nc]) =
                    *reinterpret_cast<const float4*>(B + (long)(k0 + row) * N + n0 + nc);
            }
        }
        __syncthreads();

#pragma unroll
        for (int k = 0; k < BK; k++) {
            float a[TM], bb[TN];
#pragma unroll
            for (int i = 0; i < TM; i++) a[i] = As[k][ty * TM + i];
#pragma unroll
            for (int j = 0; j < TN; j++) bb[j] = Bs[k][tx * TN + j];
#pragma unroll
            for (int i = 0; i < TM; i++)
#pragma unroll
                for (int j = 0; j < TN; j++) acc[i][j] += a[i] * bb[j];
        }
        __syncthreads();
    }

#pragma unroll
    for (int i = 0; i < TM; i++) {
        int m = m0 + ty * TM + i;
#pragma unroll
        for (int j = 0; j < TN; j += 4) {
            float4 t;
            t.x = acc[i][j + 0] * scale;
            t.y = acc[i][j + 1] * scale;
            t.z = acc[i][j + 2] * scale;
            t.w = acc[i][j + 3] * scale;
            *reinterpret_cast<float4*>(C + (long)m * N + n0 + tx * TN + j) = t;
        }
    }
}

// ---------------------------------------------------------------------------
// Row softmax, in place. Writes tf32-ROUNDED probs for s <= t and zeros only
// up to the next 128 boundary (all the P.V k-limit ever reads).
// ---------------------------------------------------------------------------
__global__ void hx_softmax_rows(float* __restrict__ P) {
    const int t = blockIdx.x;
    const int b = blockIdx.y;
    float* row = P + (long)b * TT + (long)t * TN_T;
    const int len = t + 1;
    const int zend = ((t >> 7) + 1) << 7;  // next 128-boundary
    const int tid = threadIdx.x;

    __shared__ float shmax[8];
    __shared__ float shsum[8];

    float vals[16];
    int cnt = 0;
    float mx = -1e30f;
    for (int s = tid; s < len; s += 256) {
        float v = row[s];
        vals[cnt++] = v;
        mx = fmaxf(mx, v);
    }
#pragma unroll
    for (int o = 16; o > 0; o >>= 1) mx = fmaxf(mx, __shfl_xor_sync(0xffffffffu, mx, o));
    if ((tid & 31) == 0) shmax[tid >> 5] = mx;
    __syncthreads();
    mx = shmax[0];
#pragma unroll
    for (int w = 1; w < 8; w++) mx = fmaxf(mx, shmax[w]);

    float sum = 0.f;
    for (int i = 0; i < cnt; i++) {
        vals[i] = __expf(vals[i] - mx);
        sum += vals[i];
    }
#pragma unroll
    for (int o = 16; o > 0; o >>= 1) sum += __shfl_xor_sync(0xffffffffu, sum, o);
    if ((tid & 31) == 0) shsum[tid >> 5] = sum;
    __syncthreads();
    sum = shsum[0];
#pragma unroll
    for (int w = 1; w < 8; w++) sum += shsum[w];

    const float inv = 1.f / sum;
    cnt = 0;
    for (int s = tid; s < len; s += 256) row[s] = roundtf(vals[cnt++] * inv);
    for (int s = tid; s < zend; s += 256)
        if (s >= len) row[s] = 0.f;
}

extern "C" void kernel_launch(void* const* d_in, const int* in_sizes, int n_in,
                              void* d_out, int out_size) {
    const float* x = (const float*)d_in[0];   // [4, 4096, 1024]
    const float* Wk = (const float*)d_in[1];  // [64, 1024]
    const float* Wq = (const float*)d_in[2];  // [64, 1024]
    const float* Wv = (const float*)d_in[3];  // [1024, 1024]
    float* out = (float*)d_out;               // [4, 4096, 1024] fp32

    float *Qp, *Kp, *Vtp, *Pp, *xrp, *Wvrp;
    cudaGetSymbolAddress((void**)&Qp, g_Q);
    cudaGetSymbolAddress((void**)&Kp, g_K);
    cudaGetSymbolAddress((void**)&Vtp, g_Vt);
    cudaGetSymbolAddress((void**)&Pp, g_P);
    cudaGetSymbolAddress((void**)&xrp, g_xr);
    cudaGetSymbolAddress((void**)&Wvrp, g_Wvr);

    cudaFuncSetAttribute(hx_mma_nt<false, true>,
                         cudaFuncAttributeMaxDynamicSharedMemorySize, MMA_SMEM);
    cudaFuncSetAttribute(hx_mma_nt<true, false>,
                         cudaFuncAttributeMaxDynamicSharedMemorySize, MMA_SMEM);

    const int MT = BN_B * TN_T;     // 16384 flattened token rows
    const float qk_scale = 0.125f;  // 1/sqrt(64)

    // Fused Q/K projection + tf32-rounded x_r emission (reads x once)
    hx_qk<<<MT / 128, 256>>>(x, Wq, Wk, Qp, Kp, xrp);

    // Round Wv to tf32
    hx_round4<<<(DN_D * DN_D) / 1024, 256>>>(Wv, Wvrp);

    // Vt = Wv * x^T  (tf32 warp-mma; output rounded to tf32 for P.V)
    hx_mma_nt<false, true><<<dim3(MT / 128, DN_D / 128, 1), 256, MMA_SMEM>>>(
        Wvrp, xrp, Vtp, DN_D, DN_D, MT, DN_D, 0, 0, 0);

    // S = scale * Q * K^T per batch (fp32 SIMT, causal tiles only, BK=32)
    hx_gemm<128, 128, 32, 8, 8, true, true, false><<<dim3(TN_T / 128, TN_T / 128, BN_B), 256>>>(
        Qp, Kp, Pp, TN_T, TN_T, HN_H,
        (long)TN_T * HN_H, (long)TN_T * HN_H, TT, qk_scale);

    // softmax rows in place (tf32-rounded probs, zero-fill to 128-boundary)
    hx_softmax_rows<<<dim3(TN_T, BN_B), 256>>>(Pp);

    // out = P * V per batch (tf32 warp-mma, causal k-limit, deep tiles first)
    hx_mma_nt<true, false><<<dim3(DN_D / 128, TN_T / 128, BN_B), 256, MMA_SMEM>>>(
        Pp, Vtp, out, TN_T, (int)MT, DN_D, TN_T,
        TT, (long)TN_T, (long)TN_T * DN_D);
}

// round 11
// speedup vs baseline: 4.5852x; 1.1759x over previous
#include <cuda_runtime.h>
#include <cstdint>

// Problem constants
#define BN_B 4
#define TN_T 4096
#define DN_D 1024
#define HN_H 64
static constexpr long TT = (long)TN_T * TN_T;  // 16,777,216

// Static scratch (no allocations allowed)
__device__ float g_Qh[(long)BN_B * TN_T * HN_H];           // 4 MB tf32-hi of Q
__device__ float g_Ql[(long)BN_B * TN_T * HN_H];           // 4 MB tf32-lo of Q
__device__ float g_Kh[(long)BN_B * TN_T * HN_H];           // 4 MB
__device__ float g_Kl[(long)BN_B * TN_T * HN_H];           // 4 MB
__device__ float g_Vt[(long)DN_D * BN_B * TN_T];           // 64 MB, Vt[e][b*T+t] (tf32-rounded)
__device__ float g_P[(long)BN_B * TN_T * TN_T];            // 268 MB
__device__ float g_xr[(long)BN_B * TN_T * DN_D];           // 64 MB, tf32-rounded x
__device__ float g_Wvr[(long)DN_D * DN_D];                 // 4 MB, tf32-rounded Wv

// ============================================================================
// PTX helpers (arch-stable: ldmatrix sm_75+, tf32 mma sm_80+, cp.async sm_80+)
// ============================================================================
__device__ __forceinline__ uint32_t smem_u32(const void* p) {
    uint32_t a;
    asm("{ .reg .u64 t; cvta.to.shared.u64 t, %1; cvt.u32.u64 %0, t; }"
        : "=r"(a) : "l"(p));
    return a;
}
__device__ __forceinline__ uint32_t f2tf32(float x) {
    uint32_t r; asm("cvt.rna.tf32.f32 %0, %1;" : "=r"(r) : "f"(x)); return r;
}
__device__ __forceinline__ float roundtf(float x) {
    return __uint_as_float(f2tf32(x));
}
__device__ __forceinline__ void ldmx4(uint32_t* r, uint32_t addr) {
    asm volatile("ldmatrix.sync.aligned.m8n8.x4.shared.b16 {%0,%1,%2,%3}, [%4];"
                 : "=r"(r[0]), "=r"(r[1]), "=r"(r[2]), "=r"(r[3]) : "r"(addr));
}
__device__ __forceinline__ void mma_tf32(float* c, const uint32_t* a, const uint32_t* b) {
    asm volatile(
        "mma.sync.aligned.m16n8k8.row.col.f32.tf32.tf32.f32 "
        "{%0,%1,%2,%3}, {%4,%5,%6,%7}, {%8,%9}, {%0,%1,%2,%3};"
        : "+f"(c[0]), "+f"(c[1]), "+f"(c[2]), "+f"(c[3])
        : "r"(a[0]), "r"(a[1]), "r"(a[2]), "r"(a[3]), "r"(b[0]), "r"(b[1]));
}
__device__ __forceinline__ void cpasync16(uint32_t dst, const void* src) {
    asm volatile("cp.async.cg.shared.global [%0], [%1], 16;" :: "r"(dst), "l"(src));
}
__device__ __forceinline__ uint32_t sw128(uint32_t off) {
    return off ^ ((off >> 3) & 0x70);
}

// ============================================================================
// Warp-MMA tf32 GEMM (single precision pass): C[m,n] = sum_k A[m,k]*B[n,k],
// inputs pre-rounded to tf32. 128x128 CTA, BK=32, 8 warps 2x4, 3-stage
// cp.async pipeline. KLIM: causal k-limit + reversed y order. ROUND: tf32
// epilogue rounding (Vt producer). PROVEN in rounds 7-8, unchanged.
// ============================================================================
static constexpr int MMA_SMEM = 3 * 32768;

template <bool KLIM, bool ROUND>
__global__ __launch_bounds__(256, 2)
void hx_mma_nt(const float* __restrict__ A, const float* __restrict__ B,
               float* __restrict__ C, int lda, int ldb, int ldc, int Kd,
               long sA, long sB, long sC) {
    extern __shared__ char sm[];
    const int tid = threadIdx.x;
    const int wid = tid >> 5;
    const int lane = tid & 31;
    const int myy = KLIM ? ((int)gridDim.y - 1 - (int)blockIdx.y) : (int)blockIdx.y;
    const int m0 = myy * 128;
    const int n0 = blockIdx.x * 128;
    A += (long)blockIdx.z * sA + (long)m0 * lda;
    B += (long)blockIdx.z * sB + (long)n0 * ldb;
    C += (long)blockIdx.z * sC;

    int nchunks = Kd >> 5;
    if (KLIM) { int ke = (m0 + 128) >> 5; if (ke < nchunks) nchunks = ke; }

    const int wm = (wid >> 2) * 64;
    const int wn = (wid & 3) * 32;
    const uint32_t smb = smem_u32(sm);

    float acc[4][4][4];
#pragma unroll
    for (int mt = 0; mt < 4; mt++)
#pragma unroll
        for (int nt = 0; nt < 4; nt++)
#pragma unroll
            for (int i = 0; i < 4; i++) acc[mt][nt][i] = 0.f;

    auto load_chunk = [&](int kt, int stage) {
        const float* gA = A + kt * 32;
        const float* gB = B + kt * 32;
        const uint32_t sa = smb + (uint32_t)stage * 32768u;
#pragma unroll
        for (int i = 0; i < 4; i++) {
            int idx = i * 256 + tid;
            int row = idx >> 3, c4 = idx & 7;
            uint32_t off = sw128((uint32_t)(row * 128 + c4 * 16));
            cpasync16(sa + off, gA + (long)row * lda + c4 * 4);
            cpasync16(sa + 16384u + off, gB + (long)row * ldb + c4 * 4);
        }
    };

    if (0 < nchunks) load_chunk(0, 0);
    asm volatile("cp.async.commit_group;" ::: "memory");
    if (1 < nchunks) load_chunk(1, 1);
    asm volatile("cp.async.commit_group;" ::: "memory");

    for (int kt = 0; kt < nchunks; ++kt) {
        asm volatile("cp.async.wait_group 1;" ::: "memory");
        __syncthreads();

        const int nk = kt + 2;
        if (nk < nchunks) load_chunk(nk, nk % 3);
        asm volatile("cp.async.commit_group;" ::: "memory");

        const uint32_t sa = smb + (uint32_t)(kt % 3) * 32768u;
        const uint32_t sb = sa + 16384u;
        const int sub = lane >> 3, r8 = lane & 7;

#pragma unroll
        for (int ks = 0; ks < 4; ks++) {
            uint32_t af[4][4];
#pragma unroll
            for (int mt = 0; mt < 4; mt++) {
                int row = wm + mt * 16 + ((sub & 1) << 3) + r8;
                int kseg = ks * 32 + ((sub >> 1) << 4);
                ldmx4(af[mt], sa + sw128((uint32_t)(row * 128 + kseg)));
            }
            uint32_t bf[4][2];
#pragma unroll
            for (int j2 = 0; j2 < 2; j2++) {
                int row = wn + j2 * 16 + ((sub >> 1) << 3) + r8;
                int kseg = ks * 32 + ((sub & 1) << 4);
                uint32_t r[4];
                ldmx4(r, sb + sw128((uint32_t)(row * 128 + kseg)));
                bf[j2 * 2 + 0][0] = r[0];
                bf[j2 * 2 + 0][1] = r[1];
                bf[j2 * 2 + 1][0] = r[2];
                bf[j2 * 2 + 1][1] = r[3];
            }
#pragma unroll
            for (int mt = 0; mt < 4; mt++)
#pragma unroll
                for (int nt = 0; nt < 4; nt++)
                    mma_tf32(acc[mt][nt], af[mt], bf[nt]);
        }
    }

    const int r0 = m0 + wm + (lane >> 2);
    const int c0 = n0 + wn + (lane & 3) * 2;
#pragma unroll
    for (int mt = 0; mt < 4; mt++) {
#pragma unroll
        for (int nt = 0; nt < 4; nt++) {
            long row = r0 + mt * 16;
            int col = c0 + nt * 8;
            float2 lo, hi;
            if (ROUND) {
                lo = {roundtf(acc[mt][nt][0]), roundtf(acc[mt][nt][1])};
                hi = {roundtf(acc[mt][nt][2]), roundtf(acc[mt][nt][3])};
            } else {
                lo = {acc[mt][nt][0], acc[mt][nt][1]};
                hi = {acc[mt][nt][2], acc[mt][nt][3]};
            }
            *(float2*)(C + row * ldc + col) = lo;
            *(float2*)(C + (row + 8) * ldc + col) = hi;
        }
    }
}

// ============================================================================
// hx_qk3: Q/K projection via 3xtf32 (fp32-accurate on tensor pipe).
// C[16384 x 128fused] = x * [Wq;Wk]^T. Loader splits x and W into tf32 hi/lo
// in smem (writes hi of x to g_xr for Vproj). Epilogue writes Qh/Ql/Kh/Kl.
// B tile = 128 fused rows (64 Wq then 64 Wk) x 32 floats = 1024 float4
// (R9 bug: only 512 were loaded; now rb[4] covers all 128 rows).
// ============================================================================
static constexpr int QK_SMEM = 2 * 65536;

__global__ __launch_bounds__(256)
void hx_qk3(const float* __restrict__ x, const float* __restrict__ Wq,
            const float* __restrict__ Wk, float* __restrict__ Qh,
            float* __restrict__ Ql, float* __restrict__ Kh,
            float* __restrict__ Kl, float* __restrict__ xr) {
    extern __shared__ char sm[];
    const int tid = threadIdx.x;
    const int wid = tid >> 5;
    const int lane = tid & 31;
    const int m0 = blockIdx.x * 128;
    const uint32_t smb = smem_u32(sm);

    const int wm = (wid >> 2) * 64;
    const int wn = (wid & 3) * 32;

    float acc[4][4][4];
#pragma unroll
    for (int mt = 0; mt < 4; mt++)
#pragma unroll
        for (int nt = 0; nt < 4; nt++)
#pragma unroll
            for (int i = 0; i < 4; i++) acc[mt][nt][i] = 0.f;

    float4 ra[4], rb[4];
    auto ldg_chunk = [&](int kt) {
        const float* gA = x + (long)m0 * DN_D + kt * 32;
#pragma unroll
        for (int i = 0; i < 4; i++) {
            int idx = i * 256 + tid;
            int row = idx >> 3, c4 = idx & 7;
            ra[i] = *(const float4*)(gA + (long)row * DN_D + c4 * 4);
        }
#pragma unroll
        for (int i = 0; i < 4; i++) {
            int idx = i * 256 + tid;
            int row = idx >> 3, c4 = idx & 7;
            const float* src = (row < 64) ? (Wq + (long)row * DN_D)
                                          : (Wk + (long)(row - 64) * DN_D);
            rb[i] = *(const float4*)(src + kt * 32 + c4 * 4);
        }
    };
    auto sts_chunk = [&](int kt, int st) {
        char* base = sm + st * 65536;
#pragma unroll
        for (int i = 0; i < 4; i++) {
            int idx = i * 256 + tid;
            int row = idx >> 3, c4 = idx & 7;
            uint32_t off = sw128((uint32_t)(row * 128 + c4 * 16));
            uint4 hi = {f2tf32(ra[i].x), f2tf32(ra[i].y), f2tf32(ra[i].z), f2tf32(ra[i].w)};
            uint4 lo = {f2tf32(ra[i].x - __uint_as_float(hi.x)),
                        f2tf32(ra[i].y - __uint_as_float(hi.y)),
                        f2tf32(ra[i].z - __uint_as_float(hi.z)),
                        f2tf32(ra[i].w - __uint_as_float(hi.w))};
            *(uint4*)(base + off) = hi;
            *(uint4*)(base + 16384 + off) = lo;
            *(uint4*)(xr + (long)(m0 + row) * DN_D + kt * 32 + c4 * 4) = hi;
        }
#pragma unroll
        for (int i = 0; i < 4; i++) {
            int idx = i * 256 + tid;
            int row = idx >> 3, c4 = idx & 7;
            uint32_t off = sw128((uint32_t)(row * 128 + c4 * 16));
            uint4 hi = {f2tf32(rb[i].x), f2tf32(rb[i].y), f2tf32(rb[i].z), f2tf32(rb[i].w)};
            uint4 lo = {f2tf32(rb[i].x - __uint_as_float(hi.x)),
                        f2tf32(rb[i].y - __uint_as_float(hi.y)),
                        f2tf32(rb[i].z - __uint_as_float(hi.z)),
                        f2tf32(rb[i].w - __uint_as_float(hi.w))};
            *(uint4*)(base + 32768 + off) = hi;
            *(uint4*)(base + 49152 + off) = lo;
        }
    };

    ldg_chunk(0);
    sts_chunk(0, 0);
    __syncthreads();

    const int sub = lane >> 3, r8 = lane & 7;
    for (int kt = 0; kt < 32; ++kt) {
        if (kt + 1 < 32) ldg_chunk(kt + 1);

        const uint32_t sa = smb + (uint32_t)(kt & 1) * 65536u;
#pragma unroll
        for (int ks = 0; ks < 4; ks++) {
            uint32_t afh[4][4], afl[4][4];
#pragma unroll
            for (int mt = 0; mt < 4; mt++) {
                int row = wm + mt * 16 + ((sub & 1) << 3) + r8;
                int kseg = ks * 32 + ((sub >> 1) << 4);
                uint32_t o = sw128((uint32_t)(row * 128 + kseg));
                ldmx4(afh[mt], sa + o);
                ldmx4(afl[mt], sa + 16384u + o);
            }
            uint32_t bfh[4][2], bfl[4][2];
#pragma unroll
            for (int j2 = 0; j2 < 2; j2++) {
                int row = wn + j2 * 16 + ((sub >> 1) << 3) + r8;
                int kseg = ks * 32 + ((sub & 1) << 4);
                uint32_t o = sw128((uint32_t)(row * 128 + kseg));
                uint32_t rh[4], rl[4];
                ldmx4(rh, sa + 32768u + o);
                ldmx4(rl, sa + 49152u + o);
                bfh[j2 * 2 + 0][0] = rh[0]; bfh[j2 * 2 + 0][1] = rh[1];
                bfh[j2 * 2 + 1][0] = rh[2]; bfh[j2 * 2 + 1][1] = rh[3];
                bfl[j2 * 2 + 0][0] = rl[0]; bfl[j2 * 2 + 0][1] = rl[1];
                bfl[j2 * 2 + 1][0] = rl[2]; bfl[j2 * 2 + 1][1] = rl[3];
            }
#pragma unroll
            for (int mt = 0; mt < 4; mt++)
#pragma unroll
                for (int nt = 0; nt < 4; nt++) {
                    mma_tf32(acc[mt][nt], afh[mt], bfh[nt]);
                    mma_tf32(acc[mt][nt], afh[mt], bfl[nt]);
                    mma_tf32(acc[mt][nt], afl[mt], bfh[nt]);
                }
        }

        if (kt + 1 < 32) {
            sts_chunk(kt + 1, (kt + 1) & 1);
            __syncthreads();
        }
    }

    // Epilogue: split each output into tf32 hi/lo; cols <64 -> Q, >=64 -> K
    const bool isQ = (wn < 64);
    float* dh = isQ ? Qh : Kh;
    float* dl = isQ ? Ql : Kl;
    const int cadj = isQ ? 0 : 64;
    const int r0 = m0 + wm + (lane >> 2);
    const int c0 = wn + (lane & 3) * 2 - cadj;
#pragma unroll
    for (int mt = 0; mt < 4; mt++) {
#pragma unroll
        for (int nt = 0; nt < 4; nt++) {
            int col = c0 + nt * 8;
#pragma unroll
            for (int half = 0; half < 2; half++) {
                long row = r0 + mt * 16 + half * 8;
                float v0 = acc[mt][nt][half * 2 + 0];
                float v1 = acc[mt][nt][half * 2 + 1];
                float h0 = roundtf(v0), h1 = roundtf(v1);
                float2 th = {h0, h1};
                float2 tl = {roundtf(v0 - h0), roundtf(v1 - h1)};
                *(float2*)(dh + row * HN_H + col) = th;
                *(float2*)(dl + row * HN_H + col) = tl;
            }
        }
    }
}

// ============================================================================
// hx_scores3: S = scale * Q * K^T via 3xtf32 (fp32-accurate), causal tiles.
// K-dim = 64, fully smem-resident: 8 blocks of 16KB (Qh0,Qh1,Ql0,Ql1,Kh0,..).
// One cp.async batch, one sync, then pure mma. Writes fp32 S to P.
// ============================================================================
static constexpr int SC_SMEM = 131072;

__global__ __launch_bounds__(256)
void hx_scores3(const float* __restrict__ Qh, const float* __restrict__ Ql,
                const float* __restrict__ Kh, const float* __restrict__ Kl,
                float* __restrict__ P, float scale) {
    const int m0 = blockIdx.y * 128;
    const int n0 = blockIdx.x * 128;
    if (n0 > m0) return;  // fully above causal diagonal
    extern __shared__ char sm[];
    const int tid = threadIdx.x;
    const int wid = tid >> 5;
    const int lane = tid & 31;
    const int bz = blockIdx.z;
    const uint32_t smb = smem_u32(sm);

    const long qoff = (long)(bz * TN_T + m0) * HN_H;
    const long koff = (long)(bz * TN_T + n0) * HN_H;
    const float* srcs[4] = {Qh + qoff, Ql + qoff, Kh + koff, Kl + koff};

#pragma unroll
    for (int blk = 0; blk < 8; blk++) {
        const float* src = srcs[blk >> 1];
        const int kh = blk & 1;
        const uint32_t dst = smb + (uint32_t)blk * 16384u;
#pragma unroll
        for (int i = 0; i < 4; i++) {
            int idx = i * 256 + tid;
            int row = idx >> 3, c4 = idx & 7;
            cpasync16(dst + sw128((uint32_t)(row * 128 + c4 * 16)),
                      src + (long)row * HN_H + kh * 32 + c4 * 4);
        }
    }
    asm volatile("cp.async.commit_group;" ::: "memory");
    asm volatile("cp.async.wait_group 0;" ::: "memory");
    __syncthreads();

    const int wm = (wid >> 2) * 64;
    const int wn = (wid & 3) * 32;
    const int sub = lane >> 3, r8 = lane & 7;

    float acc[4][4][4];
#pragma unroll
    for (int mt = 0; mt < 4; mt++)
#pragma unroll
        for (int nt = 0; nt < 4; nt++)
#pragma unroll
            for (int i = 0; i < 4; i++) acc[mt][nt][i] = 0.f;

#pragma unroll
    for (int kh = 0; kh < 2; kh++) {
        const uint32_t aH = smb + (uint32_t)kh * 16384u;
        const uint32_t aL = aH + 32768u;
        const uint32_t bH = aH + 65536u;
        const uint32_t bL = aH + 98304u;
#pragma unroll
        for (int ks = 0; ks < 4; ks++) {
            uint32_t afh[4][4], afl[4][4];
#pragma unroll
            for (int mt = 0; mt < 4; mt++) {
                int row = wm + mt * 16 + ((sub & 1) << 3) + r8;
                int kseg = ks * 32 + ((sub >> 1) << 4);
                uint32_t o = sw128((uint32_t)(row * 128 + kseg));
                ldmx4(afh[mt], aH + o);
                ldmx4(afl[mt], aL + o);
            }
            uint32_t bfh[4][2], bfl[4][2];
#pragma unroll
            for (int j2 = 0; j2 < 2; j2++) {
                int row = wn + j2 * 16 + ((sub >> 1) << 3) + r8;
                int kseg = ks * 32 + ((sub & 1) << 4);
                uint32_t o = sw128((uint32_t)(row * 128 + kseg));
                uint32_t rh[4], rl[4];
                ldmx4(rh, bH + o);
                ldmx4(rl, bL + o);
                bfh[j2 * 2 + 0][0] = rh[0]; bfh[j2 * 2 + 0][1] = rh[1];
                bfh[j2 * 2 + 1][0] = rh[2]; bfh[j2 * 2 + 1][1] = rh[3];
                bfl[j2 * 2 + 0][0] = rl[0]; bfl[j2 * 2 + 0][1] = rl[1];
                bfl[j2 * 2 + 1][0] = rl[2]; bfl[j2 * 2 + 1][1] = rl[3];
            }
#pragma unroll
            for (int mt = 0; mt < 4; mt++)
#pragma unroll
                for (int nt = 0; nt < 4; nt++) {
                    mma_tf32(acc[mt][nt], afh[mt], bfh[nt]);
                    mma_tf32(acc[mt][nt], afh[mt], bfl[nt]);
                    mma_tf32(acc[mt][nt], afl[mt], bfh[nt]);
                }
        }
    }

    float* C = P + (long)bz * TT;
    const int r0 = m0 + wm + (lane >> 2);
    const int c0 = n0 + wn + (lane & 3) * 2;
#pragma unroll
    for (int mt = 0; mt < 4; mt++) {
#pragma unroll
        for (int nt = 0; nt < 4; nt++) {
            long row = r0 + mt * 16;
            int col = c0 + nt * 8;
            float2 lo = {acc[mt][nt][0] * scale, acc[mt][nt][1] * scale};
            float2 hi = {acc[mt][nt][2] * scale, acc[mt][nt][3] * scale};
            *(float2*)(C + row * TN_T + col) = lo;
            *(float2*)(C + (row + 8) * TN_T + col) = hi;
        }
    }
}

// ---------------------------------------------------------------------------
// tf32 rounding pass (for Wv)
// ---------------------------------------------------------------------------
__global__ void hx_round4(const float* __restrict__ src, float* __restrict__ dst) {
    long i = ((long)blockIdx.x * 256 + threadIdx.x) * 4;
    float4 t = *(const float4*)(src + i);
    uint4 r = {f2tf32(t.x), f2tf32(t.y), f2tf32(t.z), f2tf32(t.w)};
    *(uint4*)(dst + i) = r;
}

// ---------------------------------------------------------------------------
// Row softmax, in place. Writes tf32-ROUNDED probs for s <= t and zeros only
// up to the next 128 boundary (all the P.V k-limit ever reads).
// ---------------------------------------------------------------------------
__global__ void hx_softmax_rows(float* __restrict__ P) {
    const int t = blockIdx.x;
    const int b = blockIdx.y;
    float* row = P + (long)b * TT + (long)t * TN_T;
    const int len = t + 1;
    const int zend = ((t >> 7) + 1) << 7;
    const int tid = threadIdx.x;

    __shared__ float shmax[8];
    __shared__ float shsum[8];

    float vals[16];
    int cnt = 0;
    float mx = -1e30f;
    for (int s = tid; s < len; s += 256) {
        float v = row[s];
        vals[cnt++] = v;
        mx = fmaxf(mx, v);
    }
#pragma unroll
    for (int o = 16; o > 0; o >>= 1) mx = fmaxf(mx, __shfl_xor_sync(0xffffffffu, mx, o));
    if ((tid & 31) == 0) shmax[tid >> 5] = mx;
    __syncthreads();
    mx = shmax[0];
#pragma unroll
    for (int w = 1; w < 8; w++) mx = fmaxf(mx, shmax[w]);

    float sum = 0.f;
    for (int i = 0; i < cnt; i++) {
        vals[i] = __expf(vals[i] - mx);
        sum += vals[i];
    }
#pragma unroll
    for (int o = 16; o > 0; o >>= 1) sum += __shfl_xor_sync(0xffffffffu, sum, o);
    if ((tid & 31) == 0) shsum[tid >> 5] = sum;
    __syncthreads();
    sum = shsum[0];
#pragma unroll
    for (int w = 1; w < 8; w++) sum += shsum[w];

    const float inv = 1.f / sum;
    cnt = 0;
    for (int s = tid; s < len; s += 256) row[s] = roundtf(vals[cnt++] * inv);
    for (int s = tid; s < zend; s += 256)
        if (s >= len) row[s] = 0.f;
}

extern "C" void kernel_launch(void* const* d_in, const int* in_sizes, int n_in,
                              void* d_out, int out_size) {
    const float* x = (const float*)d_in[0];   // [4, 4096, 1024]
    const float* Wk = (const float*)d_in[1];  // [64, 1024]
    const float* Wq = (const float*)d_in[2];  // [64, 1024]
    const float* Wv = (const float*)d_in[3];  // [1024, 1024]
    float* out = (float*)d_out;               // [4, 4096, 1024] fp32

    float *Qhp, *Qlp, *Khp, *Klp, *Vtp, *Pp, *xrp, *Wvrp;
    cudaGetSymbolAddress((void**)&Qhp, g_Qh);
    cudaGetSymbolAddress((void**)&Qlp, g_Ql);
    cudaGetSymbolAddress((void**)&Khp, g_Kh);
    cudaGetSymbolAddress((void**)&Klp, g_Kl);
    cudaGetSymbolAddress((void**)&Vtp, g_Vt);
    cudaGetSymbolAddress((void**)&Pp, g_P);
    cudaGetSymbolAddress((void**)&xrp, g_xr);
    cudaGetSymbolAddress((void**)&Wvrp, g_Wvr);

    cudaFuncSetAttribute(hx_mma_nt<false, true>,
                         cudaFuncAttributeMaxDynamicSharedMemorySize, MMA_SMEM);
    cudaFuncSetAttribute(hx_mma_nt<true, false>,
                         cudaFuncAttributeMaxDynamicSharedMemorySize, MMA_SMEM);
    cudaFuncSetAttribute(hx_qk3, cudaFuncAttributeMaxDynamicSharedMemorySize, QK_SMEM);
    cudaFuncSetAttribute(hx_scores3, cudaFuncAttributeMaxDynamicSharedMemorySize, SC_SMEM);

    const int MT = BN_B * TN_T;     // 16384 flattened token rows
    const float qk_scale = 0.125f;  // 1/sqrt(64)

    // Q/K projection via 3xtf32 tensor mma; also emits tf32-rounded x_r
    hx_qk3<<<MT / 128, 256, QK_SMEM>>>(x, Wq, Wk, Qhp, Qlp, Khp, Klp, xrp);

    // Round Wv to tf32
    hx_round4<<<(DN_D * DN_D) / 1024, 256>>>(Wv, Wvrp);

    // Vt = Wv * x^T  (single tf32; output rounded to tf32 for P.V)
    hx_mma_nt<false, true><<<dim3(MT / 128, DN_D / 128, 1), 256, MMA_SMEM>>>(
        Wvrp, xrp, Vtp, DN_D, DN_D, MT, DN_D, 0, 0, 0);

    // S = scale * Q * K^T per batch (3xtf32, fp32-accurate, causal tiles only)
    hx_scores3<<<dim3(TN_T / 128, TN_T / 128, BN_B), 256, SC_SMEM>>>(
        Qhp, Qlp, Khp, Klp, Pp, qk_scale);

    // softmax rows in place (tf32-rounded probs, zero-fill to 128-boundary)
    hx_softmax_rows<<<dim3(TN_T, BN_B), 256>>>(Pp);

    // out = P * V per batch (single tf32, causal k-limit, deep tiles first)
    hx_mma_nt<true, false><<<dim3(DN_D / 128, TN_T / 128, BN_B), 256, MMA_SMEM>>>(
        Pp, Vtp, out, TN_T, (int)MT, DN_D, TN_T,
        TT, (long)TN_T, (long)TN_T * DN_D);
}